// round 1
// baseline (speedup 1.0000x reference)
#include <cuda_runtime.h>
#include <math.h>

#define Bsz 8
#define Esz 2000
#define Nsz 10000
#define NRELc 25
#define Ksz 16
#define Tsz 3
#define Lsz 32
#define TAU1f 10.0f

// ---------------- scratch (static device globals; no allocation) ----------------
__device__ int   g_heads[Nsz];
__device__ int   g_tails[Nsz];
__device__ int   g_rels[Nsz];
__device__ float g_hidden_base[Esz * (NRELc - 1)];
__device__ float g_hx_acc[Bsz * NRELc];
__device__ int   g_cnt[Esz];
__device__ int   g_rowptr[Esz + 1];
__device__ int   g_fillptr[Esz];
__device__ int2  g_trips[Nsz];          // (head, rel) sorted by tail (CSR order)
__device__ float g_xt[Bsz * Ksz];       // input_x @ type_mat
__device__ float g_hidden_x0[Bsz * Lsz];
__device__ float g_wprobs[Lsz * NRELc];
__device__ float g_hidden[Lsz * Esz];
__device__ float g_sA[Bsz * Lsz * Esz];
__device__ float g_sB[Bsz * Lsz * Esz];

__device__ __forceinline__ float clip01(float x) { return fminf(fmaxf(x, 0.0f), 1.0f); }

// ---------------- kernels ----------------

__global__ void k_zero() {
    int i = blockIdx.x * blockDim.x + threadIdx.x;
    if (i < Esz * (NRELc - 1)) g_hidden_base[i] = 0.0f;
    if (i < Esz) g_cnt[i] = 0;
    if (i < Bsz * NRELc) g_hx_acc[i] = 0.0f;
}

// xt[b,k] = sum_e input_x[b,e] * type_mat[e,k]  (one block per (b,k))
__global__ void k_xt(const float* __restrict__ input_x, const float* __restrict__ type_mat) {
    int b = blockIdx.x / Ksz, k = blockIdx.x % Ksz;
    float p = 0.0f;
    for (int e = threadIdx.x; e < Esz; e += blockDim.x)
        p += input_x[b * Esz + e] * type_mat[e * Ksz + k];
    __shared__ float red[256];
    red[threadIdx.x] = p;
    __syncthreads();
    for (int off = 128; off > 0; off >>= 1) {
        if (threadIdx.x < off) red[threadIdx.x] += red[threadIdx.x + off];
        __syncthreads();
    }
    if (threadIdx.x == 0) g_xt[blockIdx.x] = red[0];
}

// One streaming pass over the three one-hot matrices -> extract heads/tails/rels
__global__ void k_extract(const float4* __restrict__ e2t,
                          const float4* __restrict__ t2e,
                          const float4* __restrict__ t2r) {
    long tid = blockIdx.x * (long)blockDim.x + threadIdx.x;
    long stride = (long)gridDim.x * blockDim.x;
    const long n1 = (long)Esz * Nsz / 4;      // e2triple [E,N]: id = e*N + n
    for (long i = tid; i < n1; i += stride) {
        float4 v = e2t[i];
        long base = i * 4;
        if (v.x != 0.0f) { long id = base + 0; g_heads[(int)(id % Nsz)] = (int)(id / Nsz); }
        if (v.y != 0.0f) { long id = base + 1; g_heads[(int)(id % Nsz)] = (int)(id / Nsz); }
        if (v.z != 0.0f) { long id = base + 2; g_heads[(int)(id % Nsz)] = (int)(id / Nsz); }
        if (v.w != 0.0f) { long id = base + 3; g_heads[(int)(id % Nsz)] = (int)(id / Nsz); }
    }
    const long n2 = (long)Nsz * Esz / 4;      // triple2e [N,E]: id = n*E + e
    for (long i = tid; i < n2; i += stride) {
        float4 v = t2e[i];
        long base = i * 4;
        if (v.x != 0.0f) { long id = base + 0; g_tails[(int)(id / Esz)] = (int)(id % Esz); }
        if (v.y != 0.0f) { long id = base + 1; g_tails[(int)(id / Esz)] = (int)(id % Esz); }
        if (v.z != 0.0f) { long id = base + 2; g_tails[(int)(id / Esz)] = (int)(id % Esz); }
        if (v.w != 0.0f) { long id = base + 3; g_tails[(int)(id / Esz)] = (int)(id % Esz); }
    }
    const long n3 = (long)Nsz * NRELc / 4;    // triple2r [N,25]: id = n*25 + r
    for (long i = tid; i < n3; i += stride) {
        float4 v = t2r[i];
        long base = i * 4;
        if (v.x != 0.0f) { long id = base + 0; g_rels[(int)(id / NRELc)] = (int)(id % NRELc); }
        if (v.y != 0.0f) { long id = base + 1; g_rels[(int)(id / NRELc)] = (int)(id % NRELc); }
        if (v.z != 0.0f) { long id = base + 2; g_rels[(int)(id / NRELc)] = (int)(id % NRELc); }
        if (v.w != 0.0f) { long id = base + 3; g_rels[(int)(id / NRELc)] = (int)(id % NRELc); }
    }
}

// Per-triple pass: hidden_base bitmap, CSR counts, hx_raw accumulation (block-local reduce)
__global__ void k_triplepass(const float* __restrict__ input_x) {
    __shared__ float sacc[Bsz * NRELc];
    for (int i = threadIdx.x; i < Bsz * NRELc; i += blockDim.x) sacc[i] = 0.0f;
    __syncthreads();
    for (int n = blockIdx.x * blockDim.x + threadIdx.x; n < Nsz; n += gridDim.x * blockDim.x) {
        int tl = g_tails[n], r = g_rels[n], hd = g_heads[n];
        if (r < NRELc - 1) g_hidden_base[tl * (NRELc - 1) + r] = 1.0f;
        atomicAdd(&g_cnt[tl], 1);
#pragma unroll
        for (int b = 0; b < Bsz; b++)
            atomicAdd(&sacc[b * NRELc + r], input_x[b * Esz + hd]);
    }
    __syncthreads();
    for (int i = threadIdx.x; i < Bsz * NRELc; i += blockDim.x)
        if (sacc[i] != 0.0f) atomicAdd(&g_hx_acc[i], sacc[i]);
}

// Exclusive scan of counts -> rowptr/fillptr, then tiny per-(b,l) side computations
__global__ void k_scan_finalize(const float* __restrict__ alpha, const float* __restrict__ beta,
                                const float* __restrict__ alpha_x, const float* __restrict__ beta_x,
                                const float* __restrict__ h_x, const float* __restrict__ h_x_type) {
    __shared__ int sc[1024];
    __shared__ float hxb[Bsz * (NRELc - 1)];
    int t = threadIdx.x;
    int c0 = (2 * t < Esz) ? g_cnt[2 * t] : 0;
    int c1 = (2 * t + 1 < Esz) ? g_cnt[2 * t + 1] : 0;
    sc[t] = c0 + c1;
    __syncthreads();
    for (int off = 1; off < 1024; off <<= 1) {
        int v = (t >= off) ? sc[t - off] : 0;
        __syncthreads();
        sc[t] += v;
        __syncthreads();
    }
    int excl = (t > 0) ? sc[t - 1] : 0;
    if (2 * t < Esz)     { g_rowptr[2 * t] = excl;          g_fillptr[2 * t] = excl; }
    if (2 * t + 1 < Esz) { g_rowptr[2 * t + 1] = excl + c0; g_fillptr[2 * t + 1] = excl + c0; }
    if (t == 0) g_rowptr[Esz] = Nsz;

    // hidden_x_base: concat(hx_raw[:,12:24], hx_raw[:,0:12]), each clipped
    if (t < Bsz * (NRELc - 1)) {
        int b = t / (NRELc - 1), j = t % (NRELc - 1);
        int col = (j < 12) ? (12 + j) : (j - 12);
        hxb[t] = clip01(g_hx_acc[b * NRELc + col]);
    }
    __syncthreads();
    // hidden_x for t=0 (only t=0 is ever applied in the reference)
    if (t < Bsz * Lsz) {
        int b = t / Lsz, l = t % Lsz;
        float a = clip01(alpha[l] / TAU1f);   // alpha[0, l]
        float bb = clip01(beta[l] / TAU1f);
        float gate = 1.0f - clip01(clip01(alpha_x[l] / TAU1f) + clip01(beta_x[l] / TAU1f));
        float htx = 0.0f;
#pragma unroll
        for (int k = 0; k < Ksz; k++)
            htx += g_xt[b * Ksz + k] * clip01(h_x_type[l * Ksz + k] / TAU1f);
        float hxl = 0.0f;
#pragma unroll
        for (int j = 0; j < NRELc - 1; j++)
            hxl += hxb[b * (NRELc - 1) + j] * clip01(h_x[l * (NRELc - 1) + j] / TAU1f);
        g_hidden_x0[t] = clip01(a * htx + bb * hxl) + gate;
    }
}

// Counting-sort fill: triples grouped by tail
__global__ void k_fill() {
    for (int n = blockIdx.x * blockDim.x + threadIdx.x; n < Nsz; n += gridDim.x * blockDim.x) {
        int tl = g_tails[n];
        int pos = atomicAdd(&g_fillptr[tl], 1);
        g_trips[pos] = make_int2(g_heads[n], g_rels[n]);
    }
}

// hidden[l,e] for step t (+ softmax of w[t] computed by block 0 warp 0)
__global__ void k_hidden(const float* __restrict__ alpha, const float* __restrict__ beta,
                         const float* __restrict__ h, const float* __restrict__ h_type,
                         const float* __restrict__ type_mat, const float* __restrict__ w, int t) {
    if (blockIdx.x == 0 && threadIdx.x < Lsz) {
        int l = threadIdx.x;
        const float* wr = w + (t * Lsz + l) * NRELc;
        float m = -1e30f;
#pragma unroll
        for (int r = 0; r < NRELc; r++) m = fmaxf(m, wr[r]);
        float s = 0.0f; float ev[NRELc];
#pragma unroll
        for (int r = 0; r < NRELc; r++) { ev[r] = expf(wr[r] - m); s += ev[r]; }
        float inv = 1.0f / s;
#pragma unroll
        for (int r = 0; r < NRELc; r++) g_wprobs[l * NRELc + r] = ev[r] * inv;
    }
    int idx = blockIdx.x * blockDim.x + threadIdx.x;
    if (idx < Lsz * Esz) {
        int e = idx % Esz, l = idx / Esz;
        float a = clip01(alpha[t * Lsz + l] / TAU1f);
        float bb = clip01(beta[t * Lsz + l] / TAU1f);
        float s1 = 0.0f;
#pragma unroll
        for (int k = 0; k < Ksz; k++)
            s1 += type_mat[e * Ksz + k] * clip01(h_type[(t * Lsz + l) * Ksz + k] / TAU1f);
        float s2 = 0.0f;
#pragma unroll
        for (int j = 0; j < NRELc - 1; j++)
            s2 += g_hidden_base[e * (NRELc - 1) + j] * clip01(h[(t * Lsz + l) * (NRELc - 1) + j] / TAU1f);
        g_hidden[idx] = clip01(a * s1 + bb * s2) + (1.0f - clip01(a + bb));
    }
}

// One propagation step: block per (b,l); prev vector in SMEM; CSR-by-tail, no atomics
__global__ void k_prop(const float* __restrict__ input_x, int t) {
    int b = blockIdx.x >> 5, l = blockIdx.x & 31;
    __shared__ float prev[Esz];
    __shared__ float wp[NRELc];
    const float* src;
    if (t == 0)      src = input_x + b * Esz;
    else if (t == 1) src = g_sA + (b * Lsz + l) * Esz;
    else             src = g_sB + (b * Lsz + l) * Esz;
    float* dst = (t == 1) ? (g_sB + (b * Lsz + l) * Esz) : (g_sA + (b * Lsz + l) * Esz);
    for (int i = threadIdx.x; i < Esz; i += blockDim.x) prev[i] = src[i];
    if (threadIdx.x < NRELc) wp[threadIdx.x] = g_wprobs[l * NRELc + threadIdx.x];
    __syncthreads();
    float scale = (t == 0) ? g_hidden_x0[b * Lsz + l] : 1.0f;
    for (int e = threadIdx.x; e < Esz; e += blockDim.x) {
        int beg = g_rowptr[e], end = g_rowptr[e + 1];
        float acc = 0.0f;
        for (int j = beg; j < end; j++) {
            int2 tr = g_trips[j];
            acc += prev[tr.x] * wp[tr.y];
        }
        dst[e] = acc * g_hidden[l * Esz + e] * scale;
    }
}

// out[b,e] = sum_l s[b,l,e] * tanh(weight[l])
__global__ void k_out(const float* __restrict__ weight, float* __restrict__ out) {
    __shared__ float tw[Lsz];
    if (threadIdx.x < Lsz) tw[threadIdx.x] = tanhf(weight[threadIdx.x]);
    __syncthreads();
    int idx = blockIdx.x * blockDim.x + threadIdx.x;
    if (idx < Bsz * Esz) {
        int b = idx / Esz, e = idx % Esz;
        float acc = 0.0f;
#pragma unroll
        for (int l = 0; l < Lsz; l++)
            acc += g_sA[(b * Lsz + l) * Esz + e] * tw[l];
        out[idx] = acc;
    }
}

// ---------------- launch ----------------
extern "C" void kernel_launch(void* const* d_in, const int* in_sizes, int n_in,
                              void* d_out, int out_size) {
    const float* input_x  = (const float*)d_in[0];   // [8,2000]
    const float* type_mat = (const float*)d_in[1];   // [2000,16]
    const float* e2triple = (const float*)d_in[2];   // [2000,10000]
    const float* triple2e = (const float*)d_in[3];   // [10000,2000]
    const float* triple2r = (const float*)d_in[4];   // [10000,25]
    const float* w        = (const float*)d_in[5];   // [3,32,25]
    const float* weight   = (const float*)d_in[6];   // [32,1]
    const float* h        = (const float*)d_in[7];   // [3,32,24]
    const float* h_x      = (const float*)d_in[8];   // [32,24]
    const float* h_type   = (const float*)d_in[9];   // [3,32,16]
    const float* h_x_type = (const float*)d_in[10];  // [32,16]
    const float* alpha    = (const float*)d_in[11];  // [3,32]
    const float* beta     = (const float*)d_in[12];  // [3,32]
    const float* alpha_x  = (const float*)d_in[13];  // [32]
    const float* beta_x   = (const float*)d_in[14];  // [32]
    // d_in[15] = flag (unused; reference ignores it)
    float* out = (float*)d_out;

    k_zero<<<(Esz * (NRELc - 1) + 255) / 256, 256>>>();
    k_xt<<<Bsz * Ksz, 256>>>(input_x, type_mat);
    k_extract<<<2048, 256>>>((const float4*)e2triple, (const float4*)triple2e,
                             (const float4*)triple2r);
    k_triplepass<<<40, 256>>>(input_x);
    k_scan_finalize<<<1, 1024>>>(alpha, beta, alpha_x, beta_x, h_x, h_x_type);
    k_fill<<<40, 256>>>();
    for (int t = 0; t < Tsz; t++) {
        k_hidden<<<(Lsz * Esz + 255) / 256, 256>>>(alpha, beta, h, h_type, type_mat, w, t);
        k_prop<<<Bsz * Lsz, 256>>>(input_x, t);
    }
    k_out<<<(Bsz * Esz + 255) / 256, 256>>>(weight, out);
}

// round 2
// speedup vs baseline: 1.0183x; 1.0183x over previous
#include <cuda_runtime.h>
#include <math.h>

#define Bsz 8
#define Esz 2000
#define Nsz 10000
#define NRELc 25
#define Ksz 16
#define Tsz 3
#define Lsz 32
#define TAU1f 10.0f

// ---------------- scratch (static device globals; no allocation) ----------------
__device__ int      g_heads[Nsz];
__device__ int      g_tails[Nsz];
__device__ int      g_rels[Nsz];
__device__ unsigned g_trips[Nsz];        // head | (rel<<16), grouped by tail (CSR)
__device__ int      g_rowptr[Esz + 1];
__device__ unsigned g_mask[Esz];         // 24-bit relation-existence bitmask per tail
__device__ int      g_tidx[Esz];         // one-hot type index per entity
__device__ int      g_ent[Bsz];          // one-hot entity index per batch row
__device__ float    g_val[Bsz];          // its value
__device__ float    g_hx0[Bsz * Lsz];    // hidden_x at t=0
__device__ float    g_sA[Bsz * Lsz * Esz];
__device__ float    g_sB[Bsz * Lsz * Esz];

__device__ __forceinline__ float clip01(float x) { return fminf(fmaxf(x, 0.0f), 1.0f); }

// ============ 1) one streaming pass over everything big: extract indices ============
__global__ void k_setup(const float4* __restrict__ e2t,
                        const float4* __restrict__ t2e,
                        const float4* __restrict__ t2r,
                        const float*  __restrict__ input_x,
                        const float*  __restrict__ type_mat) {
    unsigned tid = blockIdx.x * blockDim.x + threadIdx.x;
    unsigned stride = gridDim.x * blockDim.x;

    // tiny one-hot scans (negligible traffic)
    for (unsigned i = tid; i < Bsz * Esz; i += stride) {
        float v = input_x[i];
        if (v != 0.0f) { g_ent[i / Esz] = (int)(i % Esz); g_val[i / Esz] = v; }
    }
    for (unsigned i = tid; i < Esz * Ksz; i += stride) {
        if (type_mat[i] != 0.0f) g_tidx[i / Ksz] = (int)(i % Ksz);
    }
    // triple2r [N,25]: rels
    const unsigned n3 = Nsz * NRELc / 4;
    for (unsigned i = tid; i < n3; i += stride) {
        float4 v = t2r[i];
        unsigned base = i * 4u;
        if (v.x != 0.0f) { unsigned id = base + 0; g_rels[id / NRELc] = (int)(id % NRELc); }
        if (v.y != 0.0f) { unsigned id = base + 1; g_rels[id / NRELc] = (int)(id % NRELc); }
        if (v.z != 0.0f) { unsigned id = base + 2; g_rels[id / NRELc] = (int)(id % NRELc); }
        if (v.w != 0.0f) { unsigned id = base + 3; g_rels[id / NRELc] = (int)(id % NRELc); }
    }
    // e2triple [E,N]: heads  (80 MB)
    const unsigned n1 = (unsigned)Esz * Nsz / 4;
    for (unsigned i = tid; i < n1; i += stride) {
        float4 v = e2t[i];
        unsigned base = i * 4u;
        if (v.x != 0.0f) { unsigned id = base + 0; g_heads[id % Nsz] = (int)(id / Nsz); }
        if (v.y != 0.0f) { unsigned id = base + 1; g_heads[id % Nsz] = (int)(id / Nsz); }
        if (v.z != 0.0f) { unsigned id = base + 2; g_heads[id % Nsz] = (int)(id / Nsz); }
        if (v.w != 0.0f) { unsigned id = base + 3; g_heads[id % Nsz] = (int)(id / Nsz); }
    }
    // triple2e [N,E]: tails  (80 MB)
    const unsigned n2 = (unsigned)Nsz * Esz / 4;
    for (unsigned i = tid; i < n2; i += stride) {
        float4 v = t2e[i];
        unsigned base = i * 4u;
        if (v.x != 0.0f) { unsigned id = base + 0; g_tails[id / Esz] = (int)(id % Esz); }
        if (v.y != 0.0f) { unsigned id = base + 1; g_tails[id / Esz] = (int)(id % Esz); }
        if (v.z != 0.0f) { unsigned id = base + 2; g_tails[id / Esz] = (int)(id % Esz); }
        if (v.w != 0.0f) { unsigned id = base + 3; g_tails[id / Esz] = (int)(id % Esz); }
    }
}

// ============ 2) single block: join, scan, fill, hidden_x0 (all in SMEM) ============
__global__ void __launch_bounds__(1024, 1)
k_mid(const float* __restrict__ alpha, const float* __restrict__ beta,
      const float* __restrict__ alpha_x, const float* __restrict__ beta_x,
      const float* __restrict__ h_x, const float* __restrict__ h_x_type,
      const float* __restrict__ type_mat) {
    __shared__ int      scnt[Esz];
    __shared__ unsigned smask[Esz];
    __shared__ int      sfill[Esz];
    __shared__ int      sscan[1024];
    __shared__ float    shx[Bsz * NRELc];
    __shared__ float    shxb[Bsz * (NRELc - 1)];
    __shared__ int      sent[Bsz];
    __shared__ float    sval[Bsz];

    int t = threadIdx.x;
    for (int i = t; i < Esz; i += 1024) { scnt[i] = 0; smask[i] = 0u; }
    if (t < Bsz * NRELc) shx[t] = 0.0f;
    if (t < Bsz) { sent[t] = g_ent[t]; sval[t] = g_val[t]; }
    __syncthreads();

    // per-triple join pass
    for (int n = t; n < Nsz; n += 1024) {
        int tl = g_tails[n], r = g_rels[n], hd = g_heads[n];
        atomicAdd(&scnt[tl], 1);
        if (r < NRELc - 1) atomicOr(&smask[tl], 1u << r);
#pragma unroll
        for (int b = 0; b < Bsz; b++)
            if (hd == sent[b]) atomicAdd(&shx[b * NRELc + r], sval[b]);
    }
    __syncthreads();

    // write masks to global (used by prop)
    for (int i = t; i < Esz; i += 1024) g_mask[i] = smask[i];

    // exclusive scan of counts (2 entries / thread)
    int c0 = (2 * t < Esz) ? scnt[2 * t] : 0;
    int c1 = (2 * t + 1 < Esz) ? scnt[2 * t + 1] : 0;
    sscan[t] = c0 + c1;
    __syncthreads();
    for (int off = 1; off < 1024; off <<= 1) {
        int v = (t >= off) ? sscan[t - off] : 0;
        __syncthreads();
        sscan[t] += v;
        __syncthreads();
    }
    int excl = (t > 0) ? sscan[t - 1] : 0;
    if (2 * t < Esz)     { g_rowptr[2 * t] = excl;          sfill[2 * t] = excl; }
    if (2 * t + 1 < Esz) { g_rowptr[2 * t + 1] = excl + c0; sfill[2 * t + 1] = excl + c0; }
    if (t == 0) g_rowptr[Esz] = Nsz;

    // hidden_x_base: concat(clip01(hx_raw)[:,12:24], [:,0:12])
    if (t < Bsz * (NRELc - 1)) {
        int b = t / (NRELc - 1), j = t % (NRELc - 1);
        int col = (j < 12) ? (12 + j) : (j - 12);
        shxb[t] = clip01(shx[b * NRELc + col]);
    }
    __syncthreads();

    // hidden_x at t=0 per (b,l)
    if (t < Bsz * Lsz) {
        int b = t / Lsz, l = t % Lsz;
        float a  = clip01(alpha[l] / TAU1f);
        float bb = clip01(beta[l] / TAU1f);
        float gate = 1.0f - clip01(clip01(alpha_x[l] / TAU1f) + clip01(beta_x[l] / TAU1f));
        float htx = 0.0f;
#pragma unroll
        for (int k = 0; k < Ksz; k++)
            htx += type_mat[sent[b] * Ksz + k] * clip01(h_x_type[l * Ksz + k] / TAU1f);
        htx *= sval[b];
        float hxl = 0.0f;
#pragma unroll
        for (int j = 0; j < NRELc - 1; j++)
            hxl += shxb[b * (NRELc - 1) + j] * clip01(h_x[l * (NRELc - 1) + j] / TAU1f);
        g_hx0[t] = clip01(a * htx + bb * hxl) + gate;
    }
    __syncthreads();

    // counting-sort fill of packed trips, grouped by tail
    for (int n = t; n < Nsz; n += 1024) {
        int tl = g_tails[n];
        int pos = atomicAdd(&sfill[tl], 1);
        g_trips[pos] = (unsigned)g_heads[n] | ((unsigned)g_rels[n] << 16);
    }
}

// ============ 3) propagation step: block per (b,l); softmax+hidden on the fly ============
template <int T>
__global__ void __launch_bounds__(256)
k_prop(const float* __restrict__ input_x,
       const float* __restrict__ alpha, const float* __restrict__ beta,
       const float* __restrict__ h, const float* __restrict__ h_type,
       const float* __restrict__ w) {
    int b = blockIdx.x >> 5, l = blockIdx.x & 31;
    __shared__ float prev[Esz];
    __shared__ int   srow[Esz + 1];
    __shared__ float wp[32];
    __shared__ float shp[NRELc - 1];
    __shared__ float shtp[Ksz];

    int tid = threadIdx.x;
    // softmax of w[T,l,:] by warp 0
    if (tid < 32) {
        float v = (tid < NRELc) ? w[(T * Lsz + l) * NRELc + tid] : -1e30f;
        float m = v;
#pragma unroll
        for (int off = 16; off > 0; off >>= 1) m = fmaxf(m, __shfl_xor_sync(0xffffffff, m, off));
        float e = (tid < NRELc) ? expf(v - m) : 0.0f;
        float s = e;
#pragma unroll
        for (int off = 16; off > 0; off >>= 1) s += __shfl_xor_sync(0xffffffff, s, off);
        wp[tid] = e / s;
    }
    if (tid >= 32 && tid < 32 + NRELc - 1)
        shp[tid - 32] = clip01(h[(T * Lsz + l) * (NRELc - 1) + (tid - 32)] / TAU1f);
    if (tid >= 64 && tid < 64 + Ksz)
        shtp[tid - 64] = clip01(h_type[(T * Lsz + l) * Ksz + (tid - 64)] / TAU1f);

    const float* src;
    if (T == 0)      src = input_x + b * Esz;
    else if (T == 1) src = g_sA + (b * Lsz + l) * Esz;
    else             src = g_sB + (b * Lsz + l) * Esz;
    float* dst = (T == 1) ? (g_sB + (b * Lsz + l) * Esz) : (g_sA + (b * Lsz + l) * Esz);

    for (int i = tid; i < Esz; i += 256) prev[i] = src[i];
    for (int i = tid; i < Esz + 1; i += 256) srow[i] = g_rowptr[i];
    __syncthreads();

    float a  = clip01(alpha[T * Lsz + l] / TAU1f);
    float bb = clip01(beta[T * Lsz + l] / TAU1f);
    float oneMinus = 1.0f - clip01(a + bb);
    float scale = (T == 0) ? g_hx0[b * Lsz + l] : 1.0f;

    for (int e = tid; e < Esz; e += 256) {
        int beg = srow[e], end = srow[e + 1];
        float acc = 0.0f;
        for (int j = beg; j < end; j++) {
            unsigned u = g_trips[j];
            acc += prev[u & 0xffffu] * wp[u >> 16];
        }
        // hidden[l,e] on the fly
        float s1 = shtp[g_tidx[e]];
        float s2 = 0.0f;
        unsigned m = g_mask[e];
        while (m) { int j = __ffs(m) - 1; s2 += shp[j]; m &= m - 1; }
        float hid = clip01(a * s1 + bb * s2) + oneMinus;
        dst[e] = acc * hid * scale;
    }
}

// ============ 4) out[b,e] = sum_l s[b,l,e] * tanh(weight[l]) ============
__global__ void k_out(const float* __restrict__ weight, float* __restrict__ out) {
    __shared__ float tw[Lsz];
    if (threadIdx.x < Lsz) tw[threadIdx.x] = tanhf(weight[threadIdx.x]);
    __syncthreads();
    int idx = blockIdx.x * blockDim.x + threadIdx.x;
    if (idx < Bsz * Esz) {
        int b = idx / Esz, e = idx % Esz;
        float acc = 0.0f;
#pragma unroll
        for (int l = 0; l < Lsz; l++)
            acc += g_sA[(b * Lsz + l) * Esz + e] * tw[l];
        out[idx] = acc;
    }
}

// ---------------- launch ----------------
extern "C" void kernel_launch(void* const* d_in, const int* in_sizes, int n_in,
                              void* d_out, int out_size) {
    const float* input_x  = (const float*)d_in[0];
    const float* type_mat = (const float*)d_in[1];
    const float* e2triple = (const float*)d_in[2];
    const float* triple2e = (const float*)d_in[3];
    const float* triple2r = (const float*)d_in[4];
    const float* w        = (const float*)d_in[5];
    const float* weight   = (const float*)d_in[6];
    const float* h        = (const float*)d_in[7];
    const float* h_x      = (const float*)d_in[8];
    const float* h_type   = (const float*)d_in[9];
    const float* h_x_type = (const float*)d_in[10];
    const float* alpha    = (const float*)d_in[11];
    const float* beta     = (const float*)d_in[12];
    const float* alpha_x  = (const float*)d_in[13];
    const float* beta_x   = (const float*)d_in[14];
    float* out = (float*)d_out;

    k_setup<<<1184, 256>>>((const float4*)e2triple, (const float4*)triple2e,
                           (const float4*)triple2r, input_x, type_mat);
    k_mid<<<1, 1024>>>(alpha, beta, alpha_x, beta_x, h_x, h_x_type, type_mat);
    k_prop<0><<<Bsz * Lsz, 256>>>(input_x, alpha, beta, h, h_type, w);
    k_prop<1><<<Bsz * Lsz, 256>>>(input_x, alpha, beta, h, h_type, w);
    k_prop<2><<<Bsz * Lsz, 256>>>(input_x, alpha, beta, h, h_type, w);
    k_out<<<(Bsz * Esz + 255) / 256, 256>>>(weight, out);
}

// round 4
// speedup vs baseline: 1.4404x; 1.4145x over previous
#include <cuda_runtime.h>
#include <math.h>

#define Bsz 8
#define Esz 2000
#define Nsz 10000
#define NRELc 25
#define Ksz 16
#define Tsz 3
#define Lsz 32
#define TAU1f 10.0f
#define BL 256               // B*L columns
#define TAILS_PER_BLOCK 2

// ---------------- scratch (static device globals) ----------------
__device__ int      g_heads[Nsz];
__device__ int      g_tails[Nsz];
__device__ int      g_rels[Nsz];
__device__ unsigned g_trips[Nsz];        // head | (rel<<16), CSR by tail
__device__ int      g_rowptr[Esz + 1];
__device__ unsigned g_mask[Esz];         // 24-bit relation bitmask per tail
__device__ int      g_tidx[Esz];         // type index per entity
__device__ int      g_ent[Bsz];
__device__ float    g_val[Bsz];
__device__ float    g_hx0[BL];           // hidden_x at t=0, [b*32+l]
__device__ float    g_wp[Tsz * NRELc * Lsz];        // softmax(w[t]) stored [t][r][l]
__device__ float    g_shp[Tsz * (NRELc - 1) * Lsz]; // clip(h/10) [t][j][l]
__device__ float    g_shtp[Tsz * Ksz * Lsz];        // clip(h_type/10) [t][k][l]
__device__ float    g_ab[Tsz * Lsz * 2];            // a, bb per (t,l)
__device__ float    g_tw[Lsz];                      // tanh(weight)
__device__ float    g_sA[Esz * BL];      // s layout [e][b*32+l]
__device__ float    g_sB[Esz * BL];

__device__ __forceinline__ float clip01(float x) { return fminf(fmaxf(x, 0.0f), 1.0f); }

// ============ 1) streaming extraction of all one-hot structures ============
__global__ void k_setup(const float4* __restrict__ e2t,
                        const float4* __restrict__ t2e,
                        const float4* __restrict__ t2r,
                        const float*  __restrict__ input_x,
                        const float*  __restrict__ type_mat) {
    unsigned tid = blockIdx.x * blockDim.x + threadIdx.x;
    unsigned stride = gridDim.x * blockDim.x;

    for (unsigned i = tid; i < Bsz * Esz; i += stride) {
        float v = input_x[i];
        if (v != 0.0f) { g_ent[i / Esz] = (int)(i % Esz); g_val[i / Esz] = v; }
    }
    for (unsigned i = tid; i < Esz * Ksz; i += stride)
        if (type_mat[i] != 0.0f) g_tidx[i / Ksz] = (int)(i % Ksz);

    const unsigned n3 = Nsz * NRELc / 4;
    for (unsigned i = tid; i < n3; i += stride) {
        float4 v = t2r[i];
        unsigned base = i * 4u;
        if (v.x != 0.0f) { unsigned id = base + 0; g_rels[id / NRELc] = (int)(id % NRELc); }
        if (v.y != 0.0f) { unsigned id = base + 1; g_rels[id / NRELc] = (int)(id % NRELc); }
        if (v.z != 0.0f) { unsigned id = base + 2; g_rels[id / NRELc] = (int)(id % NRELc); }
        if (v.w != 0.0f) { unsigned id = base + 3; g_rels[id / NRELc] = (int)(id % NRELc); }
    }
    const unsigned n1 = (unsigned)Esz * Nsz / 4;   // e2triple [E,N]
    for (unsigned i = tid; i < n1; i += stride) {
        float4 v = e2t[i];
        unsigned base = i * 4u;
        if (v.x != 0.0f) { unsigned id = base + 0; g_heads[id % Nsz] = (int)(id / Nsz); }
        if (v.y != 0.0f) { unsigned id = base + 1; g_heads[id % Nsz] = (int)(id / Nsz); }
        if (v.z != 0.0f) { unsigned id = base + 2; g_heads[id % Nsz] = (int)(id / Nsz); }
        if (v.w != 0.0f) { unsigned id = base + 3; g_heads[id % Nsz] = (int)(id / Nsz); }
    }
    const unsigned n2 = (unsigned)Nsz * Esz / 4;   // triple2e [N,E]
    for (unsigned i = tid; i < n2; i += stride) {
        float4 v = t2e[i];
        unsigned base = i * 4u;
        if (v.x != 0.0f) { unsigned id = base + 0; g_tails[id / Esz] = (int)(id % Esz); }
        if (v.y != 0.0f) { unsigned id = base + 1; g_tails[id / Esz] = (int)(id % Esz); }
        if (v.z != 0.0f) { unsigned id = base + 2; g_tails[id / Esz] = (int)(id % Esz); }
        if (v.w != 0.0f) { unsigned id = base + 3; g_tails[id / Esz] = (int)(id % Esz); }
    }
}

// ============ 2) single block: join, scan, fill, tables, hx0 ============
__global__ void __launch_bounds__(1024, 1)
k_mid(const float* __restrict__ alpha, const float* __restrict__ beta,
      const float* __restrict__ alpha_x, const float* __restrict__ beta_x,
      const float* __restrict__ h_x, const float* __restrict__ h_x_type,
      const float* __restrict__ type_mat, const float* __restrict__ w,
      const float* __restrict__ h, const float* __restrict__ h_type,
      const float* __restrict__ weight) {
    __shared__ int      scnt[Esz];
    __shared__ unsigned smask[Esz];
    __shared__ int      sfill[Esz];
    __shared__ int      sscan[1024];
    __shared__ float    shx[Bsz * NRELc];
    __shared__ float    shxb[Bsz * (NRELc - 1)];
    __shared__ int      sent[Bsz];
    __shared__ float    sval[Bsz];

    int t = threadIdx.x;
    for (int i = t; i < Esz; i += 1024) { scnt[i] = 0; smask[i] = 0u; }
    if (t < Bsz * NRELc) shx[t] = 0.0f;
    if (t < Bsz) { sent[t] = g_ent[t]; sval[t] = g_val[t]; }
    __syncthreads();

    for (int n = t; n < Nsz; n += 1024) {
        int tl = g_tails[n], r = g_rels[n], hd = g_heads[n];
        atomicAdd(&scnt[tl], 1);
        if (r < NRELc - 1) atomicOr(&smask[tl], 1u << r);
#pragma unroll
        for (int b = 0; b < Bsz; b++)
            if (hd == sent[b]) atomicAdd(&shx[b * NRELc + r], sval[b]);
    }
    __syncthreads();

    for (int i = t; i < Esz; i += 1024) g_mask[i] = smask[i];

    // ---- precompute tables (full-coverage stride loops) ----
    // softmax over w[t][l] -> g_wp[t][r][l], plus a/bb
    if (t < Tsz * Lsz) {
        int tt = t / Lsz, l = t % Lsz;
        const float* wr = w + (tt * Lsz + l) * NRELc;
        float m = -1e30f;
#pragma unroll
        for (int r = 0; r < NRELc; r++) m = fmaxf(m, wr[r]);
        float s = 0.0f, ev[NRELc];
#pragma unroll
        for (int r = 0; r < NRELc; r++) { ev[r] = expf(wr[r] - m); s += ev[r]; }
        float inv = 1.0f / s;
#pragma unroll
        for (int r = 0; r < NRELc; r++)
            g_wp[(tt * NRELc + r) * Lsz + l] = ev[r] * inv;
        g_ab[(tt * Lsz + l) * 2 + 0] = clip01(alpha[tt * Lsz + l] / TAU1f);
        g_ab[(tt * Lsz + l) * 2 + 1] = clip01(beta[tt * Lsz + l] / TAU1f);
    }
    for (int i = t; i < Tsz * (NRELc - 1) * Lsz; i += 1024) {
        int tt = i / ((NRELc - 1) * Lsz);
        int rem = i % ((NRELc - 1) * Lsz);
        int j = rem / Lsz, l = rem % Lsz;
        g_shp[i] = clip01(h[(tt * Lsz + l) * (NRELc - 1) + j] / TAU1f);
    }
    for (int i = t; i < Tsz * Ksz * Lsz; i += 1024) {
        int tt = i / (Ksz * Lsz);
        int rem = i % (Ksz * Lsz);
        int k = rem / Lsz, l = rem % Lsz;
        g_shtp[i] = clip01(h_type[(tt * Lsz + l) * Ksz + k] / TAU1f);
    }
    if (t < Lsz) g_tw[t] = tanhf(weight[t]);

    // ---- exclusive scan of counts ----
    int c0 = (2 * t < Esz) ? scnt[2 * t] : 0;
    int c1 = (2 * t + 1 < Esz) ? scnt[2 * t + 1] : 0;
    sscan[t] = c0 + c1;
    __syncthreads();
    for (int off = 1; off < 1024; off <<= 1) {
        int v = (t >= off) ? sscan[t - off] : 0;
        __syncthreads();
        sscan[t] += v;
        __syncthreads();
    }
    int excl = (t > 0) ? sscan[t - 1] : 0;
    if (2 * t < Esz)     { g_rowptr[2 * t] = excl;          sfill[2 * t] = excl; }
    if (2 * t + 1 < Esz) { g_rowptr[2 * t + 1] = excl + c0; sfill[2 * t + 1] = excl + c0; }
    if (t == 0) g_rowptr[Esz] = Nsz;

    if (t < Bsz * (NRELc - 1)) {
        int b = t / (NRELc - 1), j = t % (NRELc - 1);
        int col = (j < 12) ? (12 + j) : (j - 12);
        shxb[t] = clip01(shx[b * NRELc + col]);
    }
    __syncthreads();

    // hidden_x at t=0 per (b,l)
    if (t < BL) {
        int b = t / Lsz, l = t % Lsz;
        float a  = clip01(alpha[l] / TAU1f);   // alpha[0,l]
        float bb = clip01(beta[l] / TAU1f);
        float gate = 1.0f - clip01(clip01(alpha_x[l] / TAU1f) + clip01(beta_x[l] / TAU1f));
        float htx = 0.0f;
#pragma unroll
        for (int k = 0; k < Ksz; k++)
            htx += type_mat[sent[b] * Ksz + k] * clip01(h_x_type[l * Ksz + k] / TAU1f);
        htx *= sval[b];
        float hxl = 0.0f;
#pragma unroll
        for (int j = 0; j < NRELc - 1; j++)
            hxl += shxb[b * (NRELc - 1) + j] * clip01(h_x[l * (NRELc - 1) + j] / TAU1f);
        g_hx0[t] = clip01(a * htx + bb * hxl) + gate;
    }
    __syncthreads();

    // counting-sort fill of packed trips, grouped by tail
    for (int n = t; n < Nsz; n += 1024) {
        int tl = g_tails[n];
        int pos = atomicAdd(&sfill[tl], 1);
        g_trips[pos] = (unsigned)g_heads[n] | ((unsigned)g_rels[n] << 16);
    }
}

// ============ 3) propagation: thread = (b,l) column, block = 2 tails ============
template <int T>
__global__ void __launch_bounds__(BL)
k_prop(const float* __restrict__ input_x, float* __restrict__ out) {
    const int tid = threadIdx.x;
    const int b = tid >> 5, l = tid & 31;
    const int e0 = blockIdx.x * TAILS_PER_BLOCK;

    const float a   = g_ab[(T * Lsz + l) * 2 + 0];
    const float bb  = g_ab[(T * Lsz + l) * 2 + 1];
    const float oneMinus = 1.0f - clip01(a + bb);
    const float scale = (T == 0) ? g_hx0[tid] : 1.0f;
    const float* prevbuf = (T == 1) ? g_sA : g_sB;
    float* dstbuf = (T == 0) ? g_sA : g_sB;   // T==2 writes out instead

#pragma unroll
    for (int ei = 0; ei < TAILS_PER_BLOCK; ei++) {
        int e = e0 + ei;
        int beg = g_rowptr[e], end = g_rowptr[e + 1];
        float acc = 0.0f;
        int j = beg;
        unsigned u = 0; float v = 0.0f;
        if (j < end) {
            u = g_trips[j];
            v = (T == 0) ? __ldg(&input_x[b * Esz + (u & 0xffffu)])
                         : prevbuf[(u & 0xffffu) * BL + tid];
        }
        while (j < end) {
            unsigned u_c = u; float v_c = v;
            ++j;
            if (j < end) {
                u = g_trips[j];
                v = (T == 0) ? __ldg(&input_x[b * Esz + (u & 0xffffu)])
                             : prevbuf[(u & 0xffffu) * BL + tid];
            }
            acc = fmaf(v_c, g_wp[(T * NRELc + (u_c >> 16)) * Lsz + l], acc);
        }
        // hidden[l,e] on the fly
        float s1 = g_shtp[(T * Ksz + g_tidx[e]) * Lsz + l];
        float s2 = 0.0f;
        unsigned m = g_mask[e];
        while (m) { int jj = __ffs(m) - 1; s2 += g_shp[(T * (NRELc - 1) + jj) * Lsz + l]; m &= m - 1; }
        float hid = clip01(a * s1 + bb * s2) + oneMinus;
        float val = acc * hid * scale;
        if (T == 2) {
            float r = val * g_tw[l];
#pragma unroll
            for (int off = 16; off > 0; off >>= 1)
                r += __shfl_xor_sync(0xffffffffu, r, off);
            if (l == 0) out[b * Esz + e] = r;
        } else {
            dstbuf[e * BL + tid] = val;
        }
    }
}

// ---------------- launch ----------------
extern "C" void kernel_launch(void* const* d_in, const int* in_sizes, int n_in,
                              void* d_out, int out_size) {
    const float* input_x  = (const float*)d_in[0];
    const float* type_mat = (const float*)d_in[1];
    const float* e2triple = (const float*)d_in[2];
    const float* triple2e = (const float*)d_in[3];
    const float* triple2r = (const float*)d_in[4];
    const float* w        = (const float*)d_in[5];
    const float* weight   = (const float*)d_in[6];
    const float* h        = (const float*)d_in[7];
    const float* h_x      = (const float*)d_in[8];
    const float* h_type   = (const float*)d_in[9];
    const float* h_x_type = (const float*)d_in[10];
    const float* alpha    = (const float*)d_in[11];
    const float* beta     = (const float*)d_in[12];
    const float* alpha_x  = (const float*)d_in[13];
    const float* beta_x   = (const float*)d_in[14];
    float* out = (float*)d_out;

    k_setup<<<1184, 256>>>((const float4*)e2triple, (const float4*)triple2e,
                           (const float4*)triple2r, input_x, type_mat);
    k_mid<<<1, 1024>>>(alpha, beta, alpha_x, beta_x, h_x, h_x_type,
                       type_mat, w, h, h_type, weight);
    k_prop<0><<<Esz / TAILS_PER_BLOCK, BL>>>(input_x, out);
    k_prop<1><<<Esz / TAILS_PER_BLOCK, BL>>>(input_x, out);
    k_prop<2><<<Esz / TAILS_PER_BLOCK, BL>>>(input_x, out);
}